// round 7
// baseline (speedup 1.0000x reference)
#include <cuda_runtime.h>
#include <cstdint>
#include <math.h>

#define DEV_INLINE __device__ __forceinline__

static constexpr int B_ = 16, C_ = 256, H_ = 128, W_ = 128;
static constexpr int CS = 512;
static constexpr int TOK_HF = 1024;
static constexpr int M_HF = 3 * B_ * TOK_HF;     // 49152
static constexpr int M_LF = B_ * 256;            // 4096

// ---------------- scratch ----------------
__device__ float g_z[3ULL * B_ * C_ * TOK_HF];       // [band][b][c][tok]
__device__ float g_ps[(size_t)B_ * CS * 256];        // [b][s][tok]
__device__ float g_H[(size_t)M_HF * 512];            // RAW hidden (hf)
__device__ float g_Hlf[(size_t)M_LF * 512];          // RAW hidden (lf)
__device__ float g_ktok[(size_t)M_LF * C_];
__device__ float g_gate[(size_t)M_LF * C_];
__device__ float g_alpha[3 * B_ * TOK_HF];
__device__ float g_wt[5ULL * 512 * 256];             // transposed weights [n][k]
__device__ float2 g_stats_hf[(size_t)M_HF * 2];      // per-row (sum, sumsq), 2 halves
__device__ float2 g_stats_lf[(size_t)M_LF * 2];
__device__ float g_c1[2 * 256];
__device__ float g_bp[2 * 256];

// ---------------- weight transpose (+ LN-weight folding for w2 mats) ----------------
__global__ void transpose5_kernel(const float* __restrict__ w0, const float* __restrict__ w1,
                                  const float* __restrict__ w2, const float* __restrict__ w3,
                                  const float* __restrict__ w4,
                                  const float* __restrict__ hf_lnw, const float* __restrict__ lf_lnw)
{
    __shared__ float tile[32][33];
    int mi = blockIdx.z;
    const float* in; int R, Cc; const float* lnw = nullptr;
    switch (mi) {
        case 0: in = w0; R = 256; Cc = 512; break;
        case 1: in = w1; R = 512; Cc = 256; lnw = hf_lnw; break;
        case 2: in = w2; R = 512; Cc = 256; break;
        case 3: in = w3; R = 256; Cc = 512; break;
        default: in = w4; R = 512; Cc = 256; lnw = lf_lnw; break;
    }
    float* out = g_wt + (size_t)mi * 512 * 256;
    int bx = blockIdx.x * 32, by = blockIdx.y * 32;
    if (bx >= Cc || by >= R) return;
    int tx = threadIdx.x, ty = threadIdx.y;
#pragma unroll
    for (int j = 0; j < 32; j += 8) {
        int row = by + ty + j;
        float v = in[(size_t)row * Cc + bx + tx];
        if (lnw) v *= __ldg(lnw + row);
        tile[ty + j][tx] = v;
    }
    __syncthreads();
#pragma unroll
    for (int j = 0; j < 32; j += 8)
        out[(size_t)(bx + ty + j) * R + by + tx] = tile[tx][ty + j];
}

__global__ void fold_kernel(const float* __restrict__ w2a, const float* __restrict__ lnba,
                            const float* __restrict__ b2a,
                            const float* __restrict__ w2b, const float* __restrict__ lnbb,
                            const float* __restrict__ b2b)
{
    int mi = blockIdx.x;
    int n = threadIdx.x;
    const float* wt = g_wt + (size_t)(mi ? 4 : 1) * 512 * 256;
    const float* w2 = mi ? w2b : w2a;
    const float* lnb = mi ? lnbb : lnba;
    const float* b2 = mi ? b2b : b2a;
    float s1 = 0.f, s2 = 0.f;
    for (int k = 0; k < 512; k++) {
        s1 += wt[(size_t)n * 512 + k];
        s2 += lnb[k] * w2[(size_t)k * 256 + n];
    }
    g_c1[mi * 256 + n] = s1;
    g_bp[mi * 256 + n] = b2[n] + s2;
}

// ---------------- K1: Haar bands -> abs-pooled z tokens ----------------
__global__ void haar_z_kernel(const float* __restrict__ xb)
{
    int tid = threadIdx.x;
    int tk = blockIdx.x * 256 + tid;
    int c = blockIdx.y, b = blockIdx.z;
    int ti = tk >> 5, tj = tk & 31;
    const float* base = xb + ((size_t)(b * C_ + c) * H_ + 4 * ti) * W_ + 4 * tj;
    float4 r0 = *(const float4*)(base);
    float4 r1 = *(const float4*)(base + W_);
    float4 r2 = *(const float4*)(base + 2 * W_);
    float4 r3 = *(const float4*)(base + 3 * W_);
    float zh = 0.f, zv = 0.f, zd = 0.f;
#define HBLK(p00, p01, p10, p11) \
    zh += fabsf((p00) - (p01) + (p10) - (p11)); \
    zv += fabsf((p00) + (p01) - (p10) - (p11)); \
    zd += fabsf((p00) - (p01) - (p10) + (p11));
    HBLK(r0.x, r0.y, r1.x, r1.y)
    HBLK(r0.z, r0.w, r1.z, r1.w)
    HBLK(r2.x, r2.y, r3.x, r3.y)
    HBLK(r2.z, r2.w, r3.z, r3.w)
#undef HBLK
    const float s = 0.0625f;
    size_t base_o = ((size_t)(b) * C_ + c) * TOK_HF + tk;
    const size_t BS = (size_t)B_ * C_ * TOK_HF;
    g_z[base_o]          = zh * s;
    g_z[BS + base_o]     = zv * s;
    g_z[2 * BS + base_o] = zd * s;
}

// ---------------- K2: 4x4 mean-pool of x_small ----------------
__global__ void pool_small_kernel(const float* __restrict__ xsm)
{
    int s = blockIdx.x, b = blockIdx.y;
    const float* src = xsm + ((size_t)(b * CS + s)) * 64 * 64;
    int t = threadIdx.x;
    int tj = t & 15, ti = t >> 4;
    float sum = 0.f;
#pragma unroll
    for (int r = 0; r < 4; r++) {
        float4 v = *(const float4*)(src + (4 * ti + r) * 64 + 4 * tj);
        sum += v.x + v.y + v.z + v.w;
    }
    g_ps[((size_t)(b * CS + s)) * 256 + t] = sum * (1.f / 16.f);
}

// ---------------- asm helpers ----------------
DEV_INLINE void mma8(float* c, const unsigned* a, const unsigned* b) {
    asm volatile("mma.sync.aligned.m16n8k8.row.col.f32.tf32.tf32.f32 "
                 "{%0,%1,%2,%3}, {%4,%5,%6,%7}, {%8,%9}, {%0,%1,%2,%3};"
                 : "+f"(c[0]), "+f"(c[1]), "+f"(c[2]), "+f"(c[3])
                 : "r"(a[0]), "r"(a[1]), "r"(a[2]), "r"(a[3]),
                   "r"(b[0]), "r"(b[1]));
}
DEV_INLINE void ldsm4(unsigned& r0, unsigned& r1, unsigned& r2, unsigned& r3, uint32_t addr) {
    asm volatile("ldmatrix.sync.aligned.m8n8.x4.shared.b16 {%0,%1,%2,%3}, [%4];"
                 : "=r"(r0), "=r"(r1), "=r"(r2), "=r"(r3) : "r"(addr));
}
DEV_INLINE void cp16(uint32_t s, const void* g) {
    asm volatile("cp.async.cg.shared.global [%0], [%1], 16;" :: "r"(s), "l"(g));
}
DEV_INLINE void cp_commit() { asm volatile("cp.async.commit_group;"); }
template<int NN> DEV_INLINE void cp_wait() { asm volatile("cp.async.wait_group %0;" :: "n"(NN)); }

// ---------------- unified TM x 256 tile GEMM, 256 threads ----------------
// TM=128 -> 1 CTA/SM (big-M GEMMs), TM=64 -> 2 CTAs/SM (small lf GEMMs).
// KC=32, double-buffered A+B, one __syncthreads per iteration (race-safe order).
// C = A(TMxK) @ Bt^T (Bt stored [n][k]).  AMODE: 0 z-layout, 1 ps-layout, 2 row-major.
// EPI: 0 bias store; 1 bias store + partial row stats; 2 LN-fold + cos-sim->relu;
//      3 LN-fold + sigmoid store.
template<int K, int AMODE, int EPI, int OSTRIDE, int TM>
__global__ void __launch_bounds__(256, TM == 128 ? 1 : 2)
gemm256_kernel(const float* __restrict__ A, const float* __restrict__ Bt,
               const float* __restrict__ bias, const float* __restrict__ p0,
               float* __restrict__ out, float2* __restrict__ stats,
               const float* __restrict__ c1)
{
    constexpr int KC = 32, SW = 36, SWB = SW * 4, NIT = K / KC, NN = 256;
    constexpr int MT = TM / 32;              // 16-row mma tiles per M-warp
    constexpr int GRP = 256 / TM;            // k-groups for reg-staged A
    constexpr int KPER = KC / GRP;           // k values per thread

    extern __shared__ __align__(16) float dsm[];
    float* As = dsm;                    // 2 * TM * SW
    float* Bs = As + 2 * TM * SW;       // 2 * 256 * SW
    float* sred = Bs + 2 * NN * SW;     // TM * 4
    float* ssred = sred + TM * 4;       // TM * 4
    float* spn = ssred + TM * 4;

    int tid = threadIdx.x;
    int lane = tid & 31, warp = tid >> 5;
    int wn = warp & 3, wm = warp >> 2;
    int gid = lane >> 2, q4 = lane & 3;
    int m0 = blockIdx.x * TM;
    int n0 = blockIdx.y * 256;

    const float* Ab; int astride = 0;
    if (AMODE == 0) { Ab = A + (size_t)(m0 >> 10) * (C_ * TOK_HF) + (m0 & 1023); astride = TOK_HF; }
    else if (AMODE == 1) { Ab = A + (size_t)(m0 >> 8) * (CS * 256) + (m0 & 255); astride = 256; }
    else { Ab = A + (size_t)m0 * K; }
    const float* BtB = Bt + (size_t)n0 * K;

    if (EPI == 2 && warp == 0) {
        float s = 0.f;
        for (int i = lane; i < 256; i += 32) { float v = p0[i]; s += v * v; }
#pragma unroll
        for (int o = 16; o; o >>= 1) s += __shfl_xor_sync(0xffffffffu, s, o);
        if (lane == 0) *spn = sqrtf(s);
    }

    uint32_t smem_a = (uint32_t)__cvta_generic_to_shared(As);
    uint32_t smem_b = (uint32_t)__cvta_generic_to_shared(Bs);

    int la_m = tid & (TM - 1), la_kg = tid / TM;
    float areg[KPER];
    auto load_A = [&](int k0) {
        if (AMODE <= 1) {
#pragma unroll
            for (int i = 0; i < KPER; i++)
                areg[i] = __ldg(Ab + (size_t)(k0 + la_kg * KPER + i) * astride + la_m);
        }
    };
    auto sts_A = [&](int st) {
        if (AMODE <= 1) {
            float* p = As + st * TM * SW + la_m * SW + la_kg * KPER;
#pragma unroll
            for (int i = 0; i < KPER; i += 4)
                *(float4*)(p + i) = make_float4(areg[i], areg[i + 1], areg[i + 2], areg[i + 3]);
        }
    };
    auto cp_stage = [&](int st, int k0) {
        if (AMODE == 2) {
#pragma unroll
            for (int j = 0; j < TM / 32; j++) {      // TM m x 8 kq chunks
                int idx = tid + j * 256;
                int m = idx >> 3, kq = idx & 7;
                cp16(smem_a + (uint32_t)((st * TM + m) * SW + kq * 4) * 4,
                     Ab + (size_t)m * K + k0 + kq * 4);
            }
        }
#pragma unroll
        for (int j = 0; j < 8; j++) {                // 256 n x 8 kc chunks
            int idx = tid + j * 256;
            int n = idx >> 3, kc = idx & 7;
            cp16(smem_b + (uint32_t)((st * NN + n) * SW + kc * 4) * 4,
                 BtB + (size_t)n * K + k0 + kc * 4);
        }
        cp_commit();
    };

    int ra = lane & 15;
    int ca = (lane & 16) ? 16 : 0;
    int rb = (lane & 7) + ((lane >> 4) << 3);
    int cb = (lane & 8) ? 16 : 0;

    float acc[MT][8][4];
#pragma unroll
    for (int mi = 0; mi < MT; mi++)
#pragma unroll
        for (int ni = 0; ni < 8; ni++)
#pragma unroll
            for (int e = 0; e < 4; e++) acc[mi][ni][e] = 0.f;

    // prologue: stage 0 fully staged; A regs for stage 1 pre-loaded
    load_A(0);
    cp_stage(0, 0);
    sts_A(0);
    if (NIT > 1) load_A(KC);

    for (int it = 0; it < NIT; it++) {
        int cur = it & 1;
        bool more = (it + 1 < NIT);
        cp_wait<0>();
        __syncthreads();              // publish stage cur; retire prev readers of nxt
        if (more) {
            cp_stage(cur ^ 1, (it + 1) * KC);
            sts_A(cur ^ 1);
        }
        if (it + 2 < NIT) load_A((it + 2) * KC);

        uint32_t abase = smem_a + (uint32_t)(cur * TM * SW) * 4;
        uint32_t bbase = smem_b + (uint32_t)(cur * NN * SW) * 4;
#pragma unroll
        for (int kk = 0; kk < KC; kk += 8) {
            unsigned afr[MT][4];
#pragma unroll
            for (int mi = 0; mi < MT; mi++)
                ldsm4(afr[mi][0], afr[mi][1], afr[mi][2], afr[mi][3],
                      abase + (uint32_t)((wm * (TM / 2) + mi * 16 + ra) * SWB + kk * 4 + ca));
            unsigned bfr[8][2];
#pragma unroll
            for (int nis = 0; nis < 8; nis += 2)
                ldsm4(bfr[nis][0], bfr[nis][1], bfr[nis + 1][0], bfr[nis + 1][1],
                      bbase + (uint32_t)((wn * 64 + nis * 8 + rb) * SWB + kk * 4 + cb));
#pragma unroll
            for (int mi = 0; mi < MT; mi++)
#pragma unroll
                for (int ni = 0; ni < 8; ni++)
                    mma8(acc[mi][ni], afr[mi], bfr[ni]);
        }
    }

    // ---- epilogue ----
    float mu_rs[MT][2], rstd_v[MT][2];
    if (EPI == 2 || EPI == 3) {
#pragma unroll
        for (int mi = 0; mi < MT; mi++)
#pragma unroll
            for (int h = 0; h < 2; h++) {
                int lr = wm * (TM / 2) + mi * 16 + gid + h * 8;
                float2 s0 = stats[(size_t)(m0 + lr) * 2 + 0];
                float2 s1 = stats[(size_t)(m0 + lr) * 2 + 1];
                float sum = s0.x + s1.x, ss = s0.y + s1.y;
                float mu = sum * (1.f / 512.f);
                float var = ss * (1.f / 512.f) - mu * mu;
                float rstd = rsqrtf(var + 1e-5f);
                rstd_v[mi][h] = rstd;
                mu_rs[mi][h] = mu * rstd;
            }
    }

    float rs[MT][2], rss[MT][2];
#pragma unroll
    for (int mi = 0; mi < MT; mi++) { rs[mi][0] = rs[mi][1] = 0.f; rss[mi][0] = rss[mi][1] = 0.f; }

#pragma unroll
    for (int mi = 0; mi < MT; mi++)
#pragma unroll
        for (int ni = 0; ni < 8; ni++)
#pragma unroll
            for (int e4 = 0; e4 < 4; e4++) {
                int h = e4 >> 1, e = e4 & 1;
                int col = wn * 64 + ni * 8 + q4 * 2 + e;
                float v;
                if (EPI <= 1) {
                    v = acc[mi][ni][e4] + __ldg(bias + n0 + col);
                    if (EPI == 1) { rs[mi][h] += v; rss[mi][h] += v * v; }
                } else {
                    v = rstd_v[mi][h] * acc[mi][ni][e4] - mu_rs[mi][h] * __ldg(c1 + col)
                        + __ldg(bias + col);
                    if (EPI == 2) { rs[mi][h] += v * __ldg(p0 + col); rss[mi][h] += v * v; }
                }
                acc[mi][ni][e4] = v;
            }

    if (EPI == 1 || EPI == 2) {
#pragma unroll
        for (int mi = 0; mi < MT; mi++)
#pragma unroll
            for (int h = 0; h < 2; h++) {
                float s = rs[mi][h], ss = rss[mi][h];
                s  += __shfl_xor_sync(0xffffffffu, s, 1);
                s  += __shfl_xor_sync(0xffffffffu, s, 2);
                ss += __shfl_xor_sync(0xffffffffu, ss, 1);
                ss += __shfl_xor_sync(0xffffffffu, ss, 2);
                if (q4 == 0) {
                    int lr = wm * (TM / 2) + mi * 16 + gid + h * 8;
                    sred[lr * 4 + wn] = s; ssred[lr * 4 + wn] = ss;
                }
            }
        __syncthreads();
    }

    if (EPI == 0 || EPI == 1 || EPI == 3) {
#pragma unroll
        for (int mi = 0; mi < MT; mi++)
#pragma unroll
            for (int ni = 0; ni < 8; ni++) {
                int col = wn * 64 + ni * 8 + q4 * 2;
#pragma unroll
                for (int h = 0; h < 2; h++) {
                    int lr = wm * (TM / 2) + mi * 16 + gid + h * 8;
                    float vx = acc[mi][ni][h * 2 + 0], vy = acc[mi][ni][h * 2 + 1];
                    if (EPI == 3) { vx = 1.f / (1.f + expf(-vx)); vy = 1.f / (1.f + expf(-vy)); }
                    *(float2*)(out + (size_t)(m0 + lr) * OSTRIDE + n0 + col) = make_float2(vx, vy);
                }
            }
    }
    if (EPI == 1) {
        if (tid < TM) {
            float s = 0.f, ss = 0.f;
#pragma unroll
            for (int j = 0; j < 4; j++) { s += sred[tid * 4 + j]; ss += ssred[tid * 4 + j]; }
            stats[(size_t)(m0 + tid) * 2 + blockIdx.y] = make_float2(s, ss);
        }
    }
    if (EPI == 2) {
        if (tid < TM) {
            float dot = 0.f, nsq = 0.f;
#pragma unroll
            for (int j = 0; j < 4; j++) { dot += sred[tid * 4 + j]; nsq += ssred[tid * 4 + j]; }
            float nq = sqrtf(nsq);
            float sim = dot / (fmaxf(nq, 1e-8f) * fmaxf(*spn, 1e-8f));
            out[m0 + tid] = fmaxf(sim, 0.f);
        }
    }
}

// ---------------- K5: apply alpha/gate, inverse Haar, write output ----------------
__global__ void final_kernel(const float* __restrict__ xb, float* __restrict__ out)
{
    __shared__ __align__(16) float xs[8 * 128];
    int bi = blockIdx.x, c = blockIdx.y, b = blockIdx.z;
    size_t img = ((size_t)(b * C_ + c)) * H_;
    int t = threadIdx.x;
    int lrow = t >> 5, lcol = t & 31;
    ((float4*)xs)[t] = ((const float4*)(xb + (img + 8 * bi + lrow) * W_))[lcol];
    __syncthreads();
    int rp = t >> 6, j = t & 63;
    float2 top = ((const float2*)(xs + (2 * rp) * W_))[j];
    float2 bot = ((const float2*)(xs + (2 * rp + 1) * W_))[j];
    float p00 = top.x, p01 = top.y, p10 = bot.x, p11 = bot.y;
    float a  = 0.25f * (p00 + p01 + p10 + p11);
    float hb = 0.25f * (p00 - p01 + p10 - p11);
    float vb = 0.25f * (p00 + p01 - p10 - p11);
    float db = 0.25f * (p00 - p01 - p10 + p11);
    int hr = 4 * bi + rp, hc = j;
    int tok = (hr >> 1) * 32 + (hc >> 1);
    float ah = __ldg(&g_alpha[(0 * B_ + b) * TOK_HF + tok]);
    float av = __ldg(&g_alpha[(1 * B_ + b) * TOK_HF + tok]);
    float ad = __ldg(&g_alpha[(2 * B_ + b) * TOK_HF + tok]);
    int tg = (hr >> 2) * 16 + (hc >> 2);
    float gt = __ldg(&g_gate[((size_t)(b * 256 + tg)) * C_ + c]);
    float ae = a * gt, he = hb * ah, ve = vb * av, de = db * ad;
    float2 o0 = make_float2(ae + he + ve + de, ae - he + ve - de);
    float2 o1 = make_float2(ae + he - ve - de, ae - he - ve + de);
    int row0 = 8 * bi + 2 * rp;
    ((float2*)(out + (img + row0) * W_))[j] = o0;
    ((float2*)(out + (img + row0 + 1) * W_))[j] = o1;
}

static constexpr int SMEM_G(int TM) {
    return (2 * TM * 36 + 2 * 256 * 36 + 2 * TM * 4 + 4) * 4;
}

extern "C" void kernel_launch(void* const* d_in, const int* in_sizes, int n_in,
                              void* d_out, int out_size)
{
    const float* xb      = (const float*)d_in[0];
    const float* xsm     = (const float*)d_in[1];
    const float* hf_w1   = (const float*)d_in[2];
    const float* hf_b1   = (const float*)d_in[3];
    const float* hf_ln_w = (const float*)d_in[4];
    const float* hf_ln_b = (const float*)d_in[5];
    const float* hf_w2   = (const float*)d_in[6];
    const float* hf_b2   = (const float*)d_in[7];
    const float* hf_pr   = (const float*)d_in[8];
    const float* low_w   = (const float*)d_in[9];
    const float* low_b   = (const float*)d_in[10];
    const float* lf_w1   = (const float*)d_in[11];
    const float* lf_b1   = (const float*)d_in[12];
    const float* lf_ln_w = (const float*)d_in[13];
    const float* lf_ln_b = (const float*)d_in[14];
    const float* lf_w2   = (const float*)d_in[15];
    const float* lf_b2   = (const float*)d_in[16];

    void *pz, *pps, *pH, *pHlf, *pktok, *pgate, *palpha, *pwt, *psh, *psl, *pc1, *pbp;
    cudaGetSymbolAddress(&pz, g_z);
    cudaGetSymbolAddress(&pps, g_ps);
    cudaGetSymbolAddress(&pH, g_H);
    cudaGetSymbolAddress(&pHlf, g_Hlf);
    cudaGetSymbolAddress(&pktok, g_ktok);
    cudaGetSymbolAddress(&pgate, g_gate);
    cudaGetSymbolAddress(&palpha, g_alpha);
    cudaGetSymbolAddress(&pwt, g_wt);
    cudaGetSymbolAddress(&psh, g_stats_hf);
    cudaGetSymbolAddress(&psl, g_stats_lf);
    cudaGetSymbolAddress(&pc1, g_c1);
    cudaGetSymbolAddress(&pbp, g_bp);
    const float* wt = (const float*)pwt;
    float2* sh = (float2*)psh;
    float2* sl = (float2*)psl;
    const float* c1 = (const float*)pc1;
    const float* bp = (const float*)pbp;

    cudaFuncSetAttribute((const void*)gemm256_kernel<256, 0, 1, 512, 128>,
                         cudaFuncAttributeMaxDynamicSharedMemorySize, SMEM_G(128));
    cudaFuncSetAttribute((const void*)gemm256_kernel<512, 2, 2, 256, 128>,
                         cudaFuncAttributeMaxDynamicSharedMemorySize, SMEM_G(128));
    cudaFuncSetAttribute((const void*)gemm256_kernel<512, 1, 0, 256, 64>,
                         cudaFuncAttributeMaxDynamicSharedMemorySize, SMEM_G(64));
    cudaFuncSetAttribute((const void*)gemm256_kernel<256, 2, 1, 512, 64>,
                         cudaFuncAttributeMaxDynamicSharedMemorySize, SMEM_G(64));
    cudaFuncSetAttribute((const void*)gemm256_kernel<512, 2, 3, 256, 64>,
                         cudaFuncAttributeMaxDynamicSharedMemorySize, SMEM_G(64));

    transpose5_kernel<<<dim3(16, 16, 5), dim3(32, 8)>>>(hf_w1, hf_w2, low_w, lf_w1, lf_w2,
                                                        hf_ln_w, lf_ln_w);
    fold_kernel<<<2, 256>>>(hf_w2, hf_ln_b, hf_b2, lf_w2, lf_ln_b, lf_b2);
    haar_z_kernel<<<dim3(4, 256, 16), 256>>>(xb);
    pool_small_kernel<<<dim3(512, 16), 256>>>(xsm);

    // hf chain (TM=128)
    gemm256_kernel<256, 0, 1, 512, 128><<<dim3(M_HF / 128, 2), 256, SMEM_G(128)>>>(
        (const float*)pz, wt + 0 * 512 * 256, hf_b1, nullptr, (float*)pH, sh, nullptr);
    gemm256_kernel<512, 2, 2, 256, 128><<<dim3(M_HF / 128, 1), 256, SMEM_G(128)>>>(
        (const float*)pH, wt + 1 * 512 * 256, bp + 0, hf_pr, (float*)palpha, sh, c1 + 0);

    // lf chain (TM=64)
    gemm256_kernel<512, 1, 0, 256, 64><<<dim3(M_LF / 64, 1), 256, SMEM_G(64)>>>(
        (const float*)pps, wt + 2 * 512 * 256, low_b, nullptr, (float*)pktok, nullptr, nullptr);
    gemm256_kernel<256, 2, 1, 512, 64><<<dim3(M_LF / 64, 2), 256, SMEM_G(64)>>>(
        (const float*)pktok, wt + 3 * 512 * 256, lf_b1, nullptr, (float*)pHlf, sl, nullptr);
    gemm256_kernel<512, 2, 3, 256, 64><<<dim3(M_LF / 64, 1), 256, SMEM_G(64)>>>(
        (const float*)pHlf, wt + 4 * 512 * 256, bp + 256, nullptr, (float*)pgate, sl, c1 + 256);

    final_kernel<<<dim3(16, 256, 16), 256>>>(xb, (float*)d_out);
}